// round 13
// baseline (speedup 1.0000x reference)
#include <cuda_runtime.h>
#include <cstdint>

// FHE BSGS rotate/mul/accumulate. Fixed shapes: x[64,65536] f32, diag[16,65536] f32,
// stride=1, reps=1 -> out[b,s] = sum_t x[b,(s2+2^t)&65535] * diag[t,s2], s2 = s^32768.
// R13: BPC=8, one-shot smem stage of near unions, ALL dv preloaded to registers
// (amortized over 8 batches), far taps computed batch-outer under the staging wait.
#define SLOTS 65536
#define SQ    (SLOTS / 4)     // 16384 quads per row
#define QM    (SQ - 1)
#define BATCH 64
#define BPC   8               // batches per CTA (all staged at once)
#define TPB   256             // 1 output quad per thread -> 256-quad tile
#define NEARQ 768             // near union: 256 tile + 512 reach (shifts <= 2048 slots)
#define SMEM_BYTES (BPC * NEARQ * 16)   // 98304 B (dynamic)

typedef unsigned long long u64;

__device__ __forceinline__ void cpasync16(uint32_t saddr, const float4* g) {
    asm volatile("cp.async.cg.shared.global [%0], [%1], 16;\n" :: "r"(saddr), "l"(g));
}
__device__ __forceinline__ void cp_commit() { asm volatile("cp.async.commit_group;\n"); }
__device__ __forceinline__ void cp_wait0()  { asm volatile("cp.async.wait_group 0;\n"); }

__device__ __forceinline__ u64 fma2(u64 x, u64 d, u64 a) {
    u64 r; asm("fma.rn.f32x2 %0, %1, %2, %3;" : "=l"(r) : "l"(x), "l"(d), "l"(a)); return r;
}
__device__ __forceinline__ u64 mul2(u64 x, u64 d) {
    u64 r; asm("mul.rn.f32x2 %0, %1, %2;" : "=l"(r) : "l"(x), "l"(d)); return r;
}
__device__ __forceinline__ u64 pack2(float lo, float hi) {
    u64 r; asm("mov.b64 %0, {%1, %2};" : "=l"(r) : "f"(lo), "f"(hi)); return r;
}

__global__ __launch_bounds__(TPB, 2)
void fhe_bsgs_b8(const float* __restrict__ x,
                 const float* __restrict__ diag,
                 float* __restrict__ out)
{
    extern __shared__ float4 sx[];   // [BPC][NEARQ]

    const int tid = threadIdx.x;
    const int Sq  = blockIdx.x * TPB + tid;     // output quad
    const int Tq  = (blockIdx.x * TPB) ^ 8192;  // tile base in s2 space (256-aligned)
    const int q2  = Tq + tid;                   // rolled quad for this thread
    const int b0  = blockIdx.y * BPC;

    const float4*     x4 = reinterpret_cast<const float4*>(x);
    const ulonglong2* x8 = reinterpret_cast<const ulonglong2*>(x);
    const ulonglong2* d8 = reinterpret_cast<const ulonglong2*>(diag);

    // ---- One-shot stage: near unions for all 8 batches (24 cp.asyncs/thread) ----
    #pragma unroll
    for (int b = 0; b < BPC; b++) {
        const float4* __restrict__ xb = x4 + (size_t)(b0 + b) * SQ;
        const uint32_t sb = (uint32_t)__cvta_generic_to_shared(&sx[b * NEARQ]);
        #pragma unroll
        for (int r = 0; r < 3; r++) {
            const int k = tid + 256 * r;
            cpasync16(sb + k * 16, xb + ((Tq + k) & QM));
        }
    }
    cp_commit();

    // ---- Preload ALL dv (issued under the staging wait; coalesced, L2-resident) ----
    ulonglong2 dv[16];
    #pragma unroll
    for (int t = 0; t < 16; t++)
        dv[t] = d8[t * SQ + q2];

    // ---- Far phase (t=12..15), batch-outer, pure gmem: overlaps cp.async ----
    u64 accLo[BPC], accHi[BPC];
    {
        unsigned qf[4];
        #pragma unroll
        for (int t = 0; t < 4; t++)
            qf[t] = (unsigned)(q2 + (1024 << t)) & QM;

        #pragma unroll
        for (int b = 0; b < BPC; b++) {
            const ulonglong2* __restrict__ xr = x8 + (size_t)(b0 + b) * SQ;
            const ulonglong2 X0 = xr[qf[0]];
            const ulonglong2 X1 = xr[qf[1]];
            const ulonglong2 X2 = xr[qf[2]];
            const ulonglong2 X3 = xr[qf[3]];
            u64 lo = mul2(X0.x, dv[12].x);
            u64 hi = mul2(X0.y, dv[12].y);
            lo = fma2(X1.x, dv[13].x, lo);  hi = fma2(X1.y, dv[13].y, hi);
            lo = fma2(X2.x, dv[14].x, lo);  hi = fma2(X2.y, dv[14].y, hi);
            lo = fma2(X3.x, dv[15].x, lo);  hi = fma2(X3.y, dv[15].y, hi);
            accLo[b] = lo;
            accHi[b] = hi;
        }
    }

    cp_wait0();
    __syncthreads();     // the only barrier in the kernel

    // ---- Near phase: t=0..2 (misaligned windows, via pack2) ----
    #pragma unroll
    for (int b = 0; b < BPC; b++) {
        const float4 A  = sx[b * NEARQ + tid];
        const float4 Bv = sx[b * NEARQ + tid + 1];
        u64 lo = accLo[b], hi = accHi[b];
        lo = fma2(pack2(A.y,  A.z),  dv[0].x, lo);   // t=0: (A.y,A.z | A.w,B.x)
        hi = fma2(pack2(A.w,  Bv.x), dv[0].y, hi);
        lo = fma2(pack2(A.z,  A.w),  dv[1].x, lo);   // t=1: (A.z,A.w | B.x,B.y)
        hi = fma2(pack2(Bv.x, Bv.y), dv[1].y, hi);
        lo = fma2(pack2(Bv.x, Bv.y), dv[2].x, lo);   // t=2: B
        hi = fma2(pack2(Bv.z, Bv.w), dv[2].y, hi);
        accLo[b] = lo;
        accHi[b] = hi;
    }

    // ---- Near phase: t=3..11 (offsets 2..512 quads) from smem; dv in regs ----
    #pragma unroll
    for (int t = 3; t <= 11; t++) {
        const int off = tid + (1 << (t - 2));
        #pragma unroll
        for (int b = 0; b < BPC; b++) {
            const ulonglong2 X =
                *reinterpret_cast<const ulonglong2*>(&sx[b * NEARQ + off]);
            accLo[b] = fma2(X.x, dv[t].x, accLo[b]);
            accHi[b] = fma2(X.y, dv[t].y, accHi[b]);
        }
    }

    #pragma unroll
    for (int b = 0; b < BPC; b++)
        reinterpret_cast<ulonglong2*>(out)[(size_t)(b0 + b) * SQ + Sq] =
            make_ulonglong2(accLo[b], accHi[b]);
}

extern "C" void kernel_launch(void* const* d_in, const int* in_sizes, int n_in,
                              void* d_out, int out_size)
{
    const float* x    = (const float*)d_in[0];
    const float* diag = (const float*)d_in[1];
    float* out = (float*)d_out;

    static bool attr_set = false;
    if (!attr_set) {
        cudaFuncSetAttribute(fhe_bsgs_b8,
                             cudaFuncAttributeMaxDynamicSharedMemorySize, SMEM_BYTES);
        attr_set = true;
    }

    dim3 grid(SQ / TPB, BATCH / BPC);   // (64 tiles, 8 batch-groups) = 512 CTAs
    fhe_bsgs_b8<<<grid, TPB, SMEM_BYTES>>>(x, diag, out);
}

// round 14
// speedup vs baseline: 1.0017x; 1.0017x over previous
#include <cuda_runtime.h>
#include <cstdint>

// FHE BSGS rotate/mul/accumulate. Fixed shapes: x[64,65536] f32, diag[16,65536] f32,
// stride=1, reps=1 -> out[b,s] = sum_t x[b,(s2+2^t)&65535] * diag[t,s2], s2 = s^32768.
// R14: traffic-minimized. BPC=8 (dv traffic 64->8 MB), smem covers taps t<=10 only
// (union 512 quads -> 65KB -> 3 CTAs/SM), taps t=11..15 direct coalesced LDG computed
// batch-outer UNDER the cp.async staging wait. Transient dv, pipelined 2 taps ahead.
#define SLOTS 65536
#define SQ    (SLOTS / 4)     // 16384 quads per row
#define QM    (SQ - 1)
#define BATCH 64
#define BPC   8               // batches per CTA (all staged at once)
#define TPB   256             // 1 output quad per thread -> 256-quad tile
#define NEARQ 512             // near union: 256 tile + 256 reach (taps t<=10)
#define SMEM_BYTES (BPC * NEARQ * 16)   // 65536 B

typedef unsigned long long u64;

__device__ __forceinline__ void cpasync16(uint32_t saddr, const float4* g) {
    asm volatile("cp.async.cg.shared.global [%0], [%1], 16;\n" :: "r"(saddr), "l"(g));
}
__device__ __forceinline__ void cp_commit() { asm volatile("cp.async.commit_group;\n"); }
__device__ __forceinline__ void cp_wait0()  { asm volatile("cp.async.wait_group 0;\n"); }

__device__ __forceinline__ u64 fma2(u64 x, u64 d, u64 a) {
    u64 r; asm("fma.rn.f32x2 %0, %1, %2, %3;" : "=l"(r) : "l"(x), "l"(d), "l"(a)); return r;
}
__device__ __forceinline__ u64 mul2(u64 x, u64 d) {
    u64 r; asm("mul.rn.f32x2 %0, %1, %2;" : "=l"(r) : "l"(x), "l"(d)); return r;
}
__device__ __forceinline__ u64 pack2(float lo, float hi) {
    u64 r; asm("mov.b64 %0, {%1, %2};" : "=l"(r) : "f"(lo), "f"(hi)); return r;
}

__global__ __launch_bounds__(TPB, 3)
void fhe_bsgs_tm(const float* __restrict__ x,
                 const float* __restrict__ diag,
                 float* __restrict__ out)
{
    extern __shared__ float4 sx[];   // [BPC][NEARQ]

    const int tid = threadIdx.x;
    const int Sq  = blockIdx.x * TPB + tid;     // output quad
    const int Tq  = (blockIdx.x * TPB) ^ 8192;  // tile base in s2 space (256-aligned)
    const int q2  = Tq + tid;                   // rolled quad for this thread
    const int b0  = blockIdx.y * BPC;

    const float4*     x4 = reinterpret_cast<const float4*>(x);
    const ulonglong2* x8 = reinterpret_cast<const ulonglong2*>(x);
    const float4*     d4 = reinterpret_cast<const float4*>(diag);
    const ulonglong2* d8 = reinterpret_cast<const ulonglong2*>(diag);

    // ---- One-shot stage: near unions (taps t<=10) for all 8 batches ----
    #pragma unroll
    for (int b = 0; b < BPC; b++) {
        const float4* __restrict__ xb = x4 + (size_t)(b0 + b) * SQ;
        const uint32_t sb = (uint32_t)__cvta_generic_to_shared(&sx[b * NEARQ]);
        #pragma unroll
        for (int r = 0; r < 2; r++) {
            const int k = tid + 256 * r;
            cpasync16(sb + k * 16, xb + ((Tq + k) & QM));
        }
    }
    cp_commit();

    // ---- Loads issued under the staging wait: far dv (t=11..15) + near t<=2 dv ----
    ulonglong2 dvF[5];
    #pragma unroll
    for (int t = 0; t < 5; t++)
        dvF[t] = d8[(11 + t) * SQ + q2];
    const float4 dvs0 = d4[0 * SQ + q2];
    const float4 dvs1 = d4[1 * SQ + q2];
    const float4 dvs2 = d4[2 * SQ + q2];

    // ---- Far phase (t=11..15), batch-outer, pure gmem: overlaps cp.async ----
    u64 accLo[BPC], accHi[BPC];
    {
        unsigned qf[5];
        #pragma unroll
        for (int t = 0; t < 5; t++)
            qf[t] = (unsigned)(q2 + (512 << t)) & QM;   // offsets 512..8192 quads

        #pragma unroll
        for (int b = 0; b < BPC; b++) {
            const ulonglong2* __restrict__ xr = x8 + (size_t)(b0 + b) * SQ;
            const ulonglong2 X0 = xr[qf[0]];
            const ulonglong2 X1 = xr[qf[1]];
            const ulonglong2 X2 = xr[qf[2]];
            const ulonglong2 X3 = xr[qf[3]];
            const ulonglong2 X4 = xr[qf[4]];
            u64 lo = mul2(X0.x, dvF[0].x);
            u64 hi = mul2(X0.y, dvF[0].y);
            lo = fma2(X1.x, dvF[1].x, lo);  hi = fma2(X1.y, dvF[1].y, hi);
            lo = fma2(X2.x, dvF[2].x, lo);  hi = fma2(X2.y, dvF[2].y, hi);
            lo = fma2(X3.x, dvF[3].x, lo);  hi = fma2(X3.y, dvF[3].y, hi);
            lo = fma2(X4.x, dvF[4].x, lo);  hi = fma2(X4.y, dvF[4].y, hi);
            accLo[b] = lo;
            accHi[b] = hi;
        }
    }

    cp_wait0();
    __syncthreads();     // the only barrier in the kernel

    // ---- Near phase: t=0..2 (misaligned windows) from smem ----
    #pragma unroll
    for (int b = 0; b < BPC; b++) {
        const float4 A  = sx[b * NEARQ + tid];
        const float4 Bv = sx[b * NEARQ + tid + 1];
        u64 lo = accLo[b], hi = accHi[b];
        lo = fma2(pack2(A.y,  A.z),  pack2(dvs0.x, dvs0.y), lo);  // t=0
        hi = fma2(pack2(A.w,  Bv.x), pack2(dvs0.z, dvs0.w), hi);
        lo = fma2(pack2(A.z,  A.w),  pack2(dvs1.x, dvs1.y), lo);  // t=1
        hi = fma2(pack2(Bv.x, Bv.y), pack2(dvs1.z, dvs1.w), hi);
        lo = fma2(pack2(Bv.x, Bv.y), pack2(dvs2.x, dvs2.y), lo);  // t=2
        hi = fma2(pack2(Bv.z, Bv.w), pack2(dvs2.z, dvs2.w), hi);
        accLo[b] = lo;
        accHi[b] = hi;
    }

    // ---- Near phase: t=3..10 (offsets 2..256 quads) from smem; dv 2-tap pipeline ----
    ulonglong2 dvA = d8[3 * SQ + q2];
    ulonglong2 dvB = d8[4 * SQ + q2];
    #pragma unroll
    for (int t = 3; t <= 10; t++) {
        const ulonglong2 dv = dvA;
        dvA = dvB;
        if (t + 2 <= 10)
            dvB = d8[(t + 2) * SQ + q2];
        const int off = tid + (1 << (t - 2));
        #pragma unroll
        for (int b = 0; b < BPC; b++) {
            const ulonglong2 X =
                *reinterpret_cast<const ulonglong2*>(&sx[b * NEARQ + off]);
            accLo[b] = fma2(X.x, dv.x, accLo[b]);
            accHi[b] = fma2(X.y, dv.y, accHi[b]);
        }
    }

    #pragma unroll
    for (int b = 0; b < BPC; b++)
        reinterpret_cast<ulonglong2*>(out)[(size_t)(b0 + b) * SQ + Sq] =
            make_ulonglong2(accLo[b], accHi[b]);
}

extern "C" void kernel_launch(void* const* d_in, const int* in_sizes, int n_in,
                              void* d_out, int out_size)
{
    const float* x    = (const float*)d_in[0];
    const float* diag = (const float*)d_in[1];
    float* out = (float*)d_out;

    static bool attr_set = false;
    if (!attr_set) {
        cudaFuncSetAttribute(fhe_bsgs_tm,
                             cudaFuncAttributeMaxDynamicSharedMemorySize, SMEM_BYTES);
        attr_set = true;
    }

    dim3 grid(SQ / TPB, BATCH / BPC);   // (64 tiles, 8 batch-groups) = 512 CTAs
    fhe_bsgs_tm<<<grid, TPB, SMEM_BYTES>>>(x, diag, out);
}

// round 15
// speedup vs baseline: 1.0744x; 1.0726x over previous
#include <cuda_runtime.h>
#include <cstdint>

// FHE BSGS rotate/mul/accumulate. Fixed shapes: x[64,65536] f32, diag[16,65536] f32,
// stride=1, reps=1 -> out[b,s] = sum_t x[b,(s2+2^t)&65535] * diag[t,s2], s2 = s^32768.
// R15 = R12 shape (BPC=4, tile 256, union 768, 1024 CTAs, 3 CTAs/SM) with the far
// phase (t=12..15) hoisted UNDER the cp.async staging wait (R14's overlap trick).
#define SLOTS 65536
#define SQ    (SLOTS / 4)     // 16384 quads per row
#define QM    (SQ - 1)
#define BATCH 64
#define BPC   4               // batches per CTA (all staged at once)
#define TPB   256             // 1 output quad per thread -> 256-quad tile
#define NEARQ 768             // near union: 256 tile + 512 reach (taps t<=11)
#define SMEM_BYTES (BPC * NEARQ * 16)   // 49152 B -> 3 CTAs/SM

typedef unsigned long long u64;

__device__ __forceinline__ void cpasync16(uint32_t saddr, const float4* g) {
    asm volatile("cp.async.cg.shared.global [%0], [%1], 16;\n" :: "r"(saddr), "l"(g));
}
__device__ __forceinline__ void cp_commit() { asm volatile("cp.async.commit_group;\n"); }
__device__ __forceinline__ void cp_wait0()  { asm volatile("cp.async.wait_group 0;\n"); }

__device__ __forceinline__ u64 fma2(u64 x, u64 d, u64 a) {
    u64 r; asm("fma.rn.f32x2 %0, %1, %2, %3;" : "=l"(r) : "l"(x), "l"(d), "l"(a)); return r;
}
__device__ __forceinline__ u64 mul2(u64 x, u64 d) {
    u64 r; asm("mul.rn.f32x2 %0, %1, %2;" : "=l"(r) : "l"(x), "l"(d)); return r;
}
__device__ __forceinline__ u64 pack2(float lo, float hi) {
    u64 r; asm("mov.b64 %0, {%1, %2};" : "=l"(r) : "f"(lo), "f"(hi)); return r;
}

__global__ __launch_bounds__(TPB, 3)
void fhe_bsgs_r15(const float* __restrict__ x,
                  const float* __restrict__ diag,
                  float* __restrict__ out)
{
    extern __shared__ float4 sx[];   // [BPC][NEARQ]

    const int tid = threadIdx.x;
    const int Sq  = blockIdx.x * TPB + tid;     // output quad
    const int Tq  = (blockIdx.x * TPB) ^ 8192;  // tile base in s2 space (256-aligned)
    const int q2  = Tq + tid;                   // rolled quad for this thread
    const int b0  = blockIdx.y * BPC;

    const float4*     x4 = reinterpret_cast<const float4*>(x);
    const ulonglong2* x8 = reinterpret_cast<const ulonglong2*>(x);
    const float4*     d4 = reinterpret_cast<const float4*>(diag);
    const ulonglong2* d8 = reinterpret_cast<const ulonglong2*>(diag);

    // ---- One-shot stage: near unions (taps t<=11) for all 4 batches ----
    #pragma unroll
    for (int b = 0; b < BPC; b++) {
        const float4* __restrict__ xb = x4 + (size_t)(b0 + b) * SQ;
        const uint32_t sb = (uint32_t)__cvta_generic_to_shared(&sx[b * NEARQ]);
        #pragma unroll
        for (int r = 0; r < 3; r++) {
            const int k = tid + 256 * r;
            cpasync16(sb + k * 16, xb + ((Tq + k) & QM));
        }
    }
    cp_commit();

    // ---- Under the staging wait: far-tap dv + near t<=2 dv loads ----
    ulonglong2 dvF[4];
    #pragma unroll
    for (int t = 0; t < 4; t++)
        dvF[t] = d8[(12 + t) * SQ + q2];
    const float4 dvs0 = d4[0 * SQ + q2];
    const float4 dvs1 = d4[1 * SQ + q2];
    const float4 dvs2 = d4[2 * SQ + q2];

    // ---- Far phase (t=12..15), batch-outer, pure gmem: overlaps cp.async ----
    u64 accLo[BPC], accHi[BPC];
    {
        unsigned qf[4];
        #pragma unroll
        for (int t = 0; t < 4; t++)
            qf[t] = (unsigned)(q2 + (1024 << t)) & QM;   // offsets 1024..8192 quads

        #pragma unroll
        for (int b = 0; b < BPC; b++) {
            const ulonglong2* __restrict__ xr = x8 + (size_t)(b0 + b) * SQ;
            const ulonglong2 X0 = xr[qf[0]];
            const ulonglong2 X1 = xr[qf[1]];
            const ulonglong2 X2 = xr[qf[2]];
            const ulonglong2 X3 = xr[qf[3]];
            u64 lo = mul2(X0.x, dvF[0].x);
            u64 hi = mul2(X0.y, dvF[0].y);
            lo = fma2(X1.x, dvF[1].x, lo);  hi = fma2(X1.y, dvF[1].y, hi);
            lo = fma2(X2.x, dvF[2].x, lo);  hi = fma2(X2.y, dvF[2].y, hi);
            lo = fma2(X3.x, dvF[3].x, lo);  hi = fma2(X3.y, dvF[3].y, hi);
            accLo[b] = lo;
            accHi[b] = hi;
        }
    }

    cp_wait0();
    __syncthreads();     // the only barrier in the kernel

    // ---- Near phase: t=0..2 (misaligned windows) from smem ----
    #pragma unroll
    for (int b = 0; b < BPC; b++) {
        const float4 A  = sx[b * NEARQ + tid];
        const float4 Bv = sx[b * NEARQ + tid + 1];
        u64 lo = accLo[b], hi = accHi[b];
        lo = fma2(pack2(A.y,  A.z),  pack2(dvs0.x, dvs0.y), lo);  // t=0
        hi = fma2(pack2(A.w,  Bv.x), pack2(dvs0.z, dvs0.w), hi);
        lo = fma2(pack2(A.z,  A.w),  pack2(dvs1.x, dvs1.y), lo);  // t=1
        hi = fma2(pack2(Bv.x, Bv.y), pack2(dvs1.z, dvs1.w), hi);
        lo = fma2(pack2(Bv.x, Bv.y), pack2(dvs2.x, dvs2.y), lo);  // t=2
        hi = fma2(pack2(Bv.z, Bv.w), pack2(dvs2.z, dvs2.w), hi);
        accLo[b] = lo;
        accHi[b] = hi;
    }

    // ---- Near phase: t=3..11 (offsets 2..512 quads) from smem; dv 2-tap pipeline ----
    ulonglong2 dvA = d8[3 * SQ + q2];
    ulonglong2 dvB = d8[4 * SQ + q2];
    #pragma unroll
    for (int t = 3; t <= 11; t++) {
        const ulonglong2 dv = dvA;
        dvA = dvB;
        if (t + 2 <= 11)
            dvB = d8[(t + 2) * SQ + q2];
        const int off = tid + (1 << (t - 2));
        #pragma unroll
        for (int b = 0; b < BPC; b++) {
            const ulonglong2 X =
                *reinterpret_cast<const ulonglong2*>(&sx[b * NEARQ + off]);
            accLo[b] = fma2(X.x, dv.x, accLo[b]);
            accHi[b] = fma2(X.y, dv.y, accHi[b]);
        }
    }

    #pragma unroll
    for (int b = 0; b < BPC; b++)
        reinterpret_cast<ulonglong2*>(out)[(size_t)(b0 + b) * SQ + Sq] =
            make_ulonglong2(accLo[b], accHi[b]);
}

extern "C" void kernel_launch(void* const* d_in, const int* in_sizes, int n_in,
                              void* d_out, int out_size)
{
    const float* x    = (const float*)d_in[0];
    const float* diag = (const float*)d_in[1];
    float* out = (float*)d_out;

    static bool attr_set = false;
    if (!attr_set) {
        cudaFuncSetAttribute(fhe_bsgs_r15,
                             cudaFuncAttributeMaxDynamicSharedMemorySize, SMEM_BYTES);
        attr_set = true;
    }

    dim3 grid(SQ / TPB, BATCH / BPC);   // (64 tiles, 16 batch-groups) = 1024 CTAs
    fhe_bsgs_r15<<<grid, TPB, SMEM_BYTES>>>(x, diag, out);
}

// round 16
// speedup vs baseline: 1.1065x; 1.0299x over previous
#include <cuda_runtime.h>
#include <cstdint>

// FHE BSGS rotate/mul/accumulate. Fixed shapes: x[64,65536] f32, diag[16,65536] f32,
// stride=1, reps=1 -> out[b,s] = sum_t x[b,(s2+2^t)&65535] * diag[t,s2], s2 = s^32768.
// R16 = R12 (best: BPC=4, tile 256, union 768, 1024 CTAs, 3 CTAs/SM) with far taps
// (t=12..15) rotated THROUGH the near loop: issue each tap's LDGs ~3 near-taps
// before consumption, and only after the cp.async staging traffic has drained.
#define SLOTS 65536
#define SQ    (SLOTS / 4)     // 16384 quads per row
#define QM    (SQ - 1)
#define BATCH 64
#define BPC   4               // batches per CTA (all staged at once)
#define TPB   256             // 1 output quad per thread -> 256-quad tile
#define NEARQ 768             // near union: 256 tile + 512 reach (taps t<=11)
#define SMEM_BYTES (BPC * NEARQ * 16)   // 49152 B -> 3 CTAs/SM

typedef unsigned long long u64;

__device__ __forceinline__ void cpasync16(uint32_t saddr, const float4* g) {
    asm volatile("cp.async.cg.shared.global [%0], [%1], 16;\n" :: "r"(saddr), "l"(g));
}
__device__ __forceinline__ void cp_commit() { asm volatile("cp.async.commit_group;\n"); }
__device__ __forceinline__ void cp_wait0()  { asm volatile("cp.async.wait_group 0;\n"); }

__device__ __forceinline__ u64 fma2(u64 x, u64 d, u64 a) {
    u64 r; asm("fma.rn.f32x2 %0, %1, %2, %3;" : "=l"(r) : "l"(x), "l"(d), "l"(a)); return r;
}
__device__ __forceinline__ u64 pack2(float lo, float hi) {
    u64 r; asm("mov.b64 %0, {%1, %2};" : "=l"(r) : "f"(lo), "f"(hi)); return r;
}

__global__ __launch_bounds__(TPB, 3)
void fhe_bsgs_r16(const float* __restrict__ x,
                  const float* __restrict__ diag,
                  float* __restrict__ out)
{
    extern __shared__ float4 sx[];   // [BPC][NEARQ]

    const int tid = threadIdx.x;
    const int Sq  = blockIdx.x * TPB + tid;     // output quad
    const int Tq  = (blockIdx.x * TPB) ^ 8192;  // tile base in s2 space (256-aligned)
    const int q2  = Tq + tid;                   // rolled quad for this thread
    const int b0  = blockIdx.y * BPC;

    const float4*     x4 = reinterpret_cast<const float4*>(x);
    const ulonglong2* x8 = reinterpret_cast<const ulonglong2*>(x);
    const float4*     d4 = reinterpret_cast<const float4*>(diag);
    const ulonglong2* d8 = reinterpret_cast<const ulonglong2*>(diag);

    // ---- One-shot stage: near unions (taps t<=11) for all 4 batches ----
    #pragma unroll
    for (int b = 0; b < BPC; b++) {
        const float4* __restrict__ xb = x4 + (size_t)(b0 + b) * SQ;
        const uint32_t sb = (uint32_t)__cvta_generic_to_shared(&sx[b * NEARQ]);
        #pragma unroll
        for (int r = 0; r < 3; r++) {
            const int k = tid + 256 * r;
            cpasync16(sb + k * 16, xb + ((Tq + k) & QM));
        }
    }
    cp_commit();

    // ---- Under the staging wait: dv loads only (small, coalesced) ----
    const float4 dvs0 = d4[0 * SQ + q2];
    const float4 dvs1 = d4[1 * SQ + q2];
    const float4 dvs2 = d4[2 * SQ + q2];
    ulonglong2 dvA = d8[3 * SQ + q2];      // dv pipeline for near taps
    ulonglong2 dvB = d8[4 * SQ + q2];

    cp_wait0();
    __syncthreads();     // the only barrier in the kernel

    // Far-tap rotation state: one tap in flight at a time.
    ulonglong2 dvF = d8[12 * SQ + q2];
    ulonglong2 XF[BPC];
    {
        const unsigned qf = (unsigned)(q2 + 1024) & QM;        // tap 12
        #pragma unroll
        for (int b = 0; b < BPC; b++)
            XF[b] = x8[(size_t)(b0 + b) * SQ + qf];
    }

    u64 accLo[BPC], accHi[BPC];

    // ---- Near t=0..2 (misaligned windows) from smem ----
    #pragma unroll
    for (int b = 0; b < BPC; b++) {
        const float4 A  = sx[b * NEARQ + tid];
        const float4 Bv = sx[b * NEARQ + tid + 1];
        float s0, s1, s2, s3;
        s0 = A.y  * dvs0.x;               // t=0: (A.y,A.z,A.w,B.x)
        s1 = A.z  * dvs0.y;
        s2 = A.w  * dvs0.z;
        s3 = Bv.x * dvs0.w;
        s0 = fmaf(A.z,  dvs1.x, s0);      // t=1: (A.z,A.w,B.x,B.y)
        s1 = fmaf(A.w,  dvs1.y, s1);
        s2 = fmaf(Bv.x, dvs1.z, s2);
        s3 = fmaf(Bv.y, dvs1.w, s3);
        s0 = fmaf(Bv.x, dvs2.x, s0);      // t=2: B
        s1 = fmaf(Bv.y, dvs2.y, s1);
        s2 = fmaf(Bv.z, dvs2.z, s2);
        s3 = fmaf(Bv.w, dvs2.w, s3);
        accLo[b] = pack2(s0, s1);
        accHi[b] = pack2(s2, s3);
    }

    // Near tap worker: dv pipelined two ahead.
    #define NEAR_TAP(T) do {                                            \
        const ulonglong2 dv = dvA;                                      \
        dvA = dvB;                                                      \
        if ((T) + 2 <= 11) dvB = d8[((T) + 2) * SQ + q2];               \
        const int off = tid + (1 << ((T) - 2));                         \
        _Pragma("unroll")                                               \
        for (int b = 0; b < BPC; b++) {                                 \
            const ulonglong2 X =                                        \
                *reinterpret_cast<const ulonglong2*>(&sx[b * NEARQ + off]); \
            accLo[b] = fma2(X.x, dv.x, accLo[b]);                       \
            accHi[b] = fma2(X.y, dv.y, accHi[b]);                       \
        }                                                               \
    } while (0)

    // Consume the in-flight far tap, then issue the next one.
    #define FAR_CONSUME_ISSUE(TNEXT) do {                               \
        const ulonglong2 dvc = dvF;                                     \
        ulonglong2 Xc[BPC];                                             \
        _Pragma("unroll")                                               \
        for (int b = 0; b < BPC; b++) Xc[b] = XF[b];                    \
        if ((TNEXT) <= 15) {                                            \
            dvF = d8[(TNEXT) * SQ + q2];                                \
            const unsigned qf = (unsigned)(q2 + (1 << ((TNEXT) - 2))) & QM; \
            _Pragma("unroll")                                           \
            for (int b = 0; b < BPC; b++)                               \
                XF[b] = x8[(size_t)(b0 + b) * SQ + qf];                 \
        }                                                               \
        _Pragma("unroll")                                               \
        for (int b = 0; b < BPC; b++) {                                 \
            accLo[b] = fma2(Xc[b].x, dvc.x, accLo[b]);                  \
            accHi[b] = fma2(Xc[b].y, dvc.y, accHi[b]);                  \
        }                                                               \
    } while (0)

    NEAR_TAP(3);
    NEAR_TAP(4);
    NEAR_TAP(5);
    FAR_CONSUME_ISSUE(13);      // consume tap 12 (in flight since barrier)
    NEAR_TAP(6);
    NEAR_TAP(7);
    NEAR_TAP(8);
    FAR_CONSUME_ISSUE(14);      // consume tap 13
    NEAR_TAP(9);
    NEAR_TAP(10);
    FAR_CONSUME_ISSUE(15);      // consume tap 14
    NEAR_TAP(11);
    FAR_CONSUME_ISSUE(16);      // consume tap 15 (no next)

    #undef NEAR_TAP
    #undef FAR_CONSUME_ISSUE

    #pragma unroll
    for (int b = 0; b < BPC; b++)
        reinterpret_cast<ulonglong2*>(out)[(size_t)(b0 + b) * SQ + Sq] =
            make_ulonglong2(accLo[b], accHi[b]);
}

extern "C" void kernel_launch(void* const* d_in, const int* in_sizes, int n_in,
                              void* d_out, int out_size)
{
    const float* x    = (const float*)d_in[0];
    const float* diag = (const float*)d_in[1];
    float* out = (float*)d_out;

    static bool attr_set = false;
    if (!attr_set) {
        cudaFuncSetAttribute(fhe_bsgs_r16,
                             cudaFuncAttributeMaxDynamicSharedMemorySize, SMEM_BYTES);
        attr_set = true;
    }

    dim3 grid(SQ / TPB, BATCH / BPC);   // (64 tiles, 16 batch-groups) = 1024 CTAs
    fhe_bsgs_r16<<<grid, TPB, SMEM_BYTES>>>(x, diag, out);
}